// round 11
// baseline (speedup 1.0000x reference)
#include <cuda_runtime.h>
#include <cstdint>
#include <cstddef>

#define EDIM 768
#define TLEN 1024
#define BATCH 4
#define NHEAD 6
#define HDIM 128
#define NLAYER 6
#define VOCAB 32000
#define NROWS (BATCH*TLEN)   // 4096
#define FFDIM (4*EDIM)       // 3072

// ---------------- scratch --------------------------------------------------
__device__ float g_x[NROWS*EDIM];
__device__ float g_h[NROWS*EDIM];
__device__ float g_q[NROWS*EDIM];
__device__ float g_k[NROWS*EDIM];
__device__ float g_v[NROWS*EDIM];
__device__ float g_att[NROWS*EDIM];
__device__ float g_mid[NROWS*FFDIM];
__device__ float g_rowloss[NROWS];

__device__ __forceinline__ uint32_t f2tf32(float f) {
    uint32_t r;
    asm("cvt.rna.tf32.f32 %0, %1;" : "=r"(r) : "f"(f));
    return r;
}

// ---------------- embedding ------------------------------------------------
__global__ void embed_kernel(const int* __restrict__ idx,
                             const float* __restrict__ tok,
                             const float* __restrict__ pos,
                             float* __restrict__ x) {
    int r = blockIdx.x;
    int t = r & (TLEN - 1);
    int tk = idx[r];
    const float* te = tok + (size_t)tk * EDIM;
    const float* pe = pos + (size_t)t * EDIM;
    float* xr = x + (size_t)r * EDIM;
    for (int e = threadIdx.x; e < EDIM; e += blockDim.x)
        xr[e] = te[e] + pe[e];
}

// ---------------- layernorm ------------------------------------------------
__global__ void __launch_bounds__(256) ln_kernel(const float* __restrict__ x,
                                                 const float* __restrict__ s,
                                                 const float* __restrict__ b,
                                                 float* __restrict__ out) {
    __shared__ float sh[8];
    int r = blockIdx.x;
    int tid = threadIdx.x, lane = tid & 31, wid = tid >> 5;
    const float* xr = x + (size_t)r * EDIM;
    float v[3];
#pragma unroll
    for (int i = 0; i < 3; i++) v[i] = xr[tid + i * 256];
    float sum = v[0] + v[1] + v[2];
#pragma unroll
    for (int o = 16; o; o >>= 1) sum += __shfl_xor_sync(0xffffffffu, sum, o);
    if (lane == 0) sh[wid] = sum;
    __syncthreads();
    if (tid == 0) { float t = 0.f; for (int i = 0; i < 8; i++) t += sh[i]; sh[0] = t; }
    __syncthreads();
    float mu = sh[0] * (1.0f / EDIM);
    __syncthreads();
    float sq = 0.f;
#pragma unroll
    for (int i = 0; i < 3; i++) { float d = v[i] - mu; sq += d * d; }
#pragma unroll
    for (int o = 16; o; o >>= 1) sq += __shfl_xor_sync(0xffffffffu, sq, o);
    if (lane == 0) sh[wid] = sq;
    __syncthreads();
    if (tid == 0) { float t = 0.f; for (int i = 0; i < 8; i++) t += sh[i]; sh[0] = t; }
    __syncthreads();
    float rstd = rsqrtf(sh[0] * (1.0f / EDIM) + 1e-5f);
    float* orow = out + (size_t)r * EDIM;
#pragma unroll
    for (int i = 0; i < 3; i++) {
        int e = tid + i * 256;
        orow[e] = (v[i] - mu) * rstd * s[e] + b[e];
    }
}

// ---------------- TF32 GEMM, 4-stage cp.async pipeline (R8 structure) ------
#define GBK 16
#define APAD 20
#define BPAD 136
#define BPAD64 72
#define NSTAGE 4
#define A_STG (128 * APAD)
#define B_STG (GBK * BPAD)
#define B_STG64 (GBK * BPAD64)
#define GEMM_SMEM (NSTAGE * (A_STG + B_STG) * (int)sizeof(float))
#define GEMM_SMEM64 (NSTAGE * (A_STG + B_STG64) * (int)sizeof(float))

__device__ __forceinline__ void cp16(void* dst, const void* src) {
    uint32_t d = (uint32_t)__cvta_generic_to_shared(dst);
    asm volatile("cp.async.cg.shared.global [%0], [%1], 16;" :: "r"(d), "l"(src));
}

__device__ __forceinline__ void mma_tf32(float c[4],
                                         uint32_t a0, uint32_t a1, uint32_t a2, uint32_t a3,
                                         uint32_t b0, uint32_t b1) {
    asm volatile(
        "mma.sync.aligned.m16n8k8.row.col.f32.tf32.tf32.f32 "
        "{%0,%1,%2,%3}, {%4,%5,%6,%7}, {%8,%9}, {%0,%1,%2,%3};\n"
        : "+f"(c[0]), "+f"(c[1]), "+f"(c[2]), "+f"(c[3])
        : "r"(a0), "r"(a1), "r"(a2), "r"(a3), "r"(b0), "r"(b1));
}

// flags: 1=bias, 2=relu, 4=residual-add, 8=tf32-round output
// 128x128 tile (R8-exact)
__device__ __forceinline__ void gemm_core(
    const float* __restrict__ A, const float* __restrict__ Bm,
    const float* __restrict__ bias, const float* __restrict__ res,
    float* __restrict__ C, int N, int K, int flags, int bx, int by) {
    extern __shared__ float smem_dyn[];
    float* AsAll = smem_dyn;
    float* BsAll = smem_dyn + NSTAGE * A_STG;

    int tid = threadIdx.x;
    int lane = tid & 31, wid = tid >> 5;
    int wm = (wid & 1) * 64;
    int wn = (wid >> 1) * 32;
    int gid = lane >> 2;
    int tig = lane & 3;

    const float* Ab = A + (size_t)(by * 128) * K;
    const float* Bb = Bm + bx * 128;

    int aR0 = tid >> 2;
    int aC0 = (tid & 3) * 4;
    int bR0 = tid >> 5;
    int bC0 = (tid & 31) * 4;

    float c[4][4][4];
#pragma unroll
    for (int mt = 0; mt < 4; mt++)
#pragma unroll
        for (int nt = 0; nt < 4; nt++)
#pragma unroll
            for (int i = 0; i < 4; i++) c[mt][nt][i] = 0.f;

    int nIter = K / GBK;

#pragma unroll
    for (int s = 0; s < NSTAGE - 1; s++) {
        if (s < nIter) {
            int k0 = s * GBK;
            float* As = AsAll + s * A_STG;
            float* Bs = BsAll + s * B_STG;
            cp16(&As[aR0 * APAD + aC0], Ab + (size_t)aR0 * K + k0 + aC0);
            cp16(&As[(aR0 + 64) * APAD + aC0], Ab + (size_t)(aR0 + 64) * K + k0 + aC0);
            cp16(&Bs[bR0 * BPAD + bC0], Bb + (size_t)(k0 + bR0) * N + bC0);
            cp16(&Bs[(bR0 + 8) * BPAD + bC0], Bb + (size_t)(k0 + bR0 + 8) * N + bC0);
        }
        asm volatile("cp.async.commit_group;");
    }

    for (int i = 0; i < nIter; i++) {
        if (i + NSTAGE - 1 < nIter) {
            int k0 = (i + NSTAGE - 1) * GBK;
            int s = (i + NSTAGE - 1) & (NSTAGE - 1);
            float* As = AsAll + s * A_STG;
            float* Bs = BsAll + s * B_STG;
            cp16(&As[aR0 * APAD + aC0], Ab + (size_t)aR0 * K + k0 + aC0);
            cp16(&As[(aR0 + 64) * APAD + aC0], Ab + (size_t)(aR0 + 64) * K + k0 + aC0);
            cp16(&Bs[bR0 * BPAD + bC0], Bb + (size_t)(k0 + bR0) * N + bC0);
            cp16(&Bs[(bR0 + 8) * BPAD + bC0], Bb + (size_t)(k0 + bR0 + 8) * N + bC0);
        }
        asm volatile("cp.async.commit_group;");
        asm volatile("cp.async.wait_group %0;" :: "n"(NSTAGE - 1));
        __syncthreads();

        int cur = i & (NSTAGE - 1);
        const float* As = AsAll + cur * A_STG;
        const float* Bs = BsAll + cur * B_STG;

#pragma unroll
        for (int kk = 0; kk < GBK; kk += 8) {
            uint32_t af[4][4];
#pragma unroll
            for (int mt = 0; mt < 4; mt++) {
                int rb = (wm + mt * 16 + gid) * APAD;
                af[mt][0] = f2tf32(As[rb + kk + tig]);
                af[mt][1] = f2tf32(As[rb + 8 * APAD + kk + tig]);
                af[mt][2] = f2tf32(As[rb + kk + tig + 4]);
                af[mt][3] = f2tf32(As[rb + 8 * APAD + kk + tig + 4]);
            }
            uint32_t bf[4][2];
#pragma unroll
            for (int nt = 0; nt < 4; nt++) {
                int cb = wn + nt * 8 + gid;
                bf[nt][0] = f2tf32(Bs[(kk + tig) * BPAD + cb]);
                bf[nt][1] = f2tf32(Bs[(kk + tig + 4) * BPAD + cb]);
            }
#pragma unroll
            for (int mt = 0; mt < 4; mt++)
#pragma unroll
                for (int nt = 0; nt < 4; nt++)
                    mma_tf32(c[mt][nt], af[mt][0], af[mt][1], af[mt][2], af[mt][3],
                             bf[nt][0], bf[nt][1]);
        }
        __syncthreads();
    }

#pragma unroll
    for (int mt = 0; mt < 4; mt++) {
#pragma unroll
        for (int nt = 0; nt < 4; nt++) {
            int row0 = by * 128 + wm + mt * 16 + gid;
            int col = bx * 128 + wn + nt * 8 + tig * 2;
            float2 bb = make_float2(0.f, 0.f);
            if (flags & 1) bb = *reinterpret_cast<const float2*>(bias + col);
#pragma unroll
            for (int half = 0; half < 2; half++) {
                int row = row0 + half * 8;
                float v0 = c[mt][nt][half * 2 + 0] + bb.x;
                float v1 = c[mt][nt][half * 2 + 1] + bb.y;
                if (flags & 2) { v0 = fmaxf(v0, 0.f); v1 = fmaxf(v1, 0.f); }
                size_t base = (size_t)row * N + col;
                if (flags & 4) {
                    float2 rr = *reinterpret_cast<const float2*>(res + base);
                    v0 += rr.x; v1 += rr.y;
                }
                if (flags & 8) {
                    v0 = __uint_as_float(f2tf32(v0));
                    v1 = __uint_as_float(f2tf32(v1));
                }
                float2 o2; o2.x = v0; o2.y = v1;
                *reinterpret_cast<float2*>(C + base) = o2;
            }
        }
    }
}

// 128x64 tile variant: 8 warps as 4m x 2n -> 384/1536-CTA grids on N=768/3072
// GEMMs, killing the 65%-utilization wave quantization of the 192-CTA launches.
// Same K-loop order as gemm_core -> bit-identical accumulation.
__device__ __forceinline__ void gemm_core64(
    const float* __restrict__ A, const float* __restrict__ Bm,
    const float* __restrict__ bias, const float* __restrict__ res,
    float* __restrict__ C, int N, int K, int flags, int bx, int by) {
    extern __shared__ float smem_dyn[];
    float* AsAll = smem_dyn;
    float* BsAll = smem_dyn + NSTAGE * A_STG;

    int tid = threadIdx.x;
    int lane = tid & 31, wid = tid >> 5;
    int wm = (wid >> 1) * 32;   // 4 m-groups of 32 rows
    int wn = (wid & 1) * 32;    // 2 n-groups of 32 cols
    int gid = lane >> 2;
    int tig = lane & 3;

    const float* Ab = A + (size_t)(by * 128) * K;
    const float* Bb = Bm + bx * 64;

    int aR0 = tid >> 2;
    int aC0 = (tid & 3) * 4;
    int bR0 = tid >> 4;          // 16 rows of B tile
    int bC0 = (tid & 15) * 4;    // 64 floats per row

    float c[2][4][4];
#pragma unroll
    for (int mt = 0; mt < 2; mt++)
#pragma unroll
        for (int nt = 0; nt < 4; nt++)
#pragma unroll
            for (int i = 0; i < 4; i++) c[mt][nt][i] = 0.f;

    int nIter = K / GBK;

#pragma unroll
    for (int s = 0; s < NSTAGE - 1; s++) {
        if (s < nIter) {
            int k0 = s * GBK;
            float* As = AsAll + s * A_STG;
            float* Bs = BsAll + s * B_STG64;
            cp16(&As[aR0 * APAD + aC0], Ab + (size_t)aR0 * K + k0 + aC0);
            cp16(&As[(aR0 + 64) * APAD + aC0], Ab + (size_t)(aR0 + 64) * K + k0 + aC0);
            cp16(&Bs[bR0 * BPAD64 + bC0], Bb + (size_t)(k0 + bR0) * N + bC0);
        }
        asm volatile("cp.async.commit_group;");
    }

    for (int i = 0; i < nIter; i++) {
        if (i + NSTAGE - 1 < nIter) {
            int k0 = (i + NSTAGE - 1) * GBK;
            int s = (i + NSTAGE - 1) & (NSTAGE - 1);
            float* As = AsAll + s * A_STG;
            float* Bs = BsAll + s * B_STG64;
            cp16(&As[aR0 * APAD + aC0], Ab + (size_t)aR0 * K + k0 + aC0);
            cp16(&As[(aR0 + 64) * APAD + aC0], Ab + (size_t)(aR0 + 64) * K + k0 + aC0);
            cp16(&Bs[bR0 * BPAD64 + bC0], Bb + (size_t)(k0 + bR0) * N + bC0);
        }
        asm volatile("cp.async.commit_group;");
        asm volatile("cp.async.wait_group %0;" :: "n"(NSTAGE - 1));
        __syncthreads();

        int cur = i & (NSTAGE - 1);
        const float* As = AsAll + cur * A_STG;
        const float* Bs = BsAll + cur * B_STG64;

#pragma unroll
        for (int kk = 0; kk < GBK; kk += 8) {
            uint32_t af[2][4];
#pragma unroll
            for (int mt = 0; mt < 2; mt++) {
                int rb = (wm + mt * 16 + gid) * APAD;
                af[mt][0] = f2tf32(As[rb + kk + tig]);
                af[mt][1] = f2tf32(As[rb + 8 * APAD + kk + tig]);
                af[mt][2] = f2tf32(As[rb + kk + tig + 4]);
                af[mt][3] = f2tf32(As[rb + 8 * APAD + kk + tig + 4]);
            }
            uint32_t bf[4][2];
#pragma unroll
            for (int nt = 0; nt < 4; nt++) {
                int cb = wn + nt * 8 + gid;
                bf[nt][0] = f2tf32(Bs[(kk + tig) * BPAD64 + cb]);
                bf[nt][1] = f2tf32(Bs[(kk + tig + 4) * BPAD64 + cb]);
            }
#pragma unroll
            for (int mt = 0; mt < 2; mt++)
#pragma unroll
                for (int nt = 0; nt < 4; nt++)
                    mma_tf32(c[mt][nt], af[mt][0], af[mt][1], af[mt][2], af[mt][3],
                             bf[nt][0], bf[nt][1]);
        }
        __syncthreads();
    }

#pragma unroll
    for (int mt = 0; mt < 2; mt++) {
#pragma unroll
        for (int nt = 0; nt < 4; nt++) {
            int row0 = by * 128 + wm + mt * 16 + gid;
            int col = bx * 64 + wn + nt * 8 + tig * 2;
            float2 bb = make_float2(0.f, 0.f);
            if (flags & 1) bb = *reinterpret_cast<const float2*>(bias + col);
#pragma unroll
            for (int half = 0; half < 2; half++) {
                int row = row0 + half * 8;
                float v0 = c[mt][nt][half * 2 + 0] + bb.x;
                float v1 = c[mt][nt][half * 2 + 1] + bb.y;
                if (flags & 2) { v0 = fmaxf(v0, 0.f); v1 = fmaxf(v1, 0.f); }
                size_t base = (size_t)row * N + col;
                if (flags & 4) {
                    float2 rr = *reinterpret_cast<const float2*>(res + base);
                    v0 += rr.x; v1 += rr.y;
                }
                if (flags & 8) {
                    v0 = __uint_as_float(f2tf32(v0));
                    v1 = __uint_as_float(f2tf32(v1));
                }
                float2 o2; o2.x = v0; o2.y = v1;
                *reinterpret_cast<float2*>(C + base) = o2;
            }
        }
    }
}

__global__ void __launch_bounds__(256) tgemm_kernel(
    const float* __restrict__ A, const float* __restrict__ Bm,
    const float* __restrict__ bias, const float* __restrict__ res,
    float* __restrict__ C, int N, int K, int flags) {
    gemm_core(A, Bm, bias, res, C, N, K, flags, blockIdx.x, blockIdx.y);
}

__global__ void __launch_bounds__(256) tgemm64_kernel(
    const float* __restrict__ A, const float* __restrict__ Bm,
    const float* __restrict__ bias, const float* __restrict__ res,
    float* __restrict__ C, int N, int K, int flags) {
    gemm_core64(A, Bm, bias, res, C, N, K, flags, blockIdx.x, blockIdx.y);
}

__global__ void __launch_bounds__(256) qkv_kernel(
    const float* __restrict__ h,
    const float* __restrict__ Wq, const float* __restrict__ Wk, const float* __restrict__ Wv,
    const float* __restrict__ bq, const float* __restrict__ bk, const float* __restrict__ bv,
    float* __restrict__ q, float* __restrict__ k, float* __restrict__ v) {
    const float* W; const float* bb; float* o;
    if (blockIdx.z == 0)      { W = Wq; bb = bq; o = q; }
    else if (blockIdx.z == 1) { W = Wk; bb = bk; o = k; }
    else                      { W = Wv; bb = bv; o = v; }
    gemm_core(h, W, bb, nullptr, o, EDIM, EDIM, 1 | 8, blockIdx.x, blockIdx.y);
}

// ---------------- tf32 flash attention (R8-exact: online softmax) -----------
#define ABR 128
#define ABC 32
#define QKPAD 132
#define PPAD 36
#define ATTN_SMEM ((ABR*QKPAD + 4*ABC*QKPAD + ABR*PPAD) * (int)sizeof(float))

__global__ void __launch_bounds__(256) attn_tc_kernel(const float* __restrict__ q,
                                                      const float* __restrict__ k,
                                                      const float* __restrict__ v,
                                                      float* __restrict__ out) {
    extern __shared__ float dyn[];
    float* Qs = dyn;
    float* Ksb = Qs + ABR * QKPAD;
    float* Vsb = Ksb + 2 * ABC * QKPAD;
    float* Ps = Vsb + 2 * ABC * QKPAD;

    int qb = blockIdx.x, h = blockIdx.y, b = blockIdx.z;
    int tid = threadIdx.x, lane = tid & 31, wid = tid >> 5;
    int gid = lane >> 2, tig = lane & 3;
    int wq = wid * 16;
    int q0 = qb * ABR;
    size_t baserow = (size_t)b * TLEN;
    int off = h * HDIM;
    const float scale = 0.08838834764831845f;

    for (int f = tid; f < ABR * 32; f += 256) {
        int r = f >> 5, c4 = (f & 31) * 4;
        float4 t = *reinterpret_cast<const float4*>(q + (baserow + q0 + r) * EDIM + off + c4);
        float* dst = &Qs[r * QKPAD + c4];
        dst[0] = t.x; dst[1] = t.y; dst[2] = t.z; dst[3] = t.w;
    }

    float o_acc[16][4];
#pragma unroll
    for (int n = 0; n < 16; n++)
#pragma unroll
        for (int i = 0; i < 4; i++) o_acc[n][i] = 0.f;
    float m0 = -1e30f, m1 = -1e30f, l0 = 0.f, l1 = 0.f;

    int ntile = 4 * qb + 4;

    {
        for (int f = tid; f < ABC * 32; f += 256) {
            int r = f >> 5, c4 = (f & 31) * 4;
            size_t g = (baserow + r) * EDIM + off + c4;
            cp16(&Ksb[r * QKPAD + c4], k + g);
            cp16(&Vsb[r * QKPAD + c4], v + g);
        }
        asm volatile("cp.async.commit_group;");
    }

    for (int kt = 0; kt < ntile; kt++) {
        int cur = kt & 1;
        if (kt + 1 < ntile) {
            int nxt = cur ^ 1;
            float* Kd = Ksb + nxt * ABC * QKPAD;
            float* Vd = Vsb + nxt * ABC * QKPAD;
            for (int f = tid; f < ABC * 32; f += 256) {
                int r = f >> 5, c4 = (f & 31) * 4;
                size_t g = (baserow + (kt + 1) * ABC + r) * EDIM + off + c4;
                cp16(&Kd[r * QKPAD + c4], k + g);
                cp16(&Vd[r * QKPAD + c4], v + g);
            }
            asm volatile("cp.async.commit_group;");
            asm volatile("cp.async.wait_group 1;");
        } else {
            asm volatile("cp.async.wait_group 0;");
        }
        __syncthreads();

        const float* Kb = Ksb + cur * ABC * QKPAD;
        const float* Vb = Vsb + cur * ABC * QKPAD;

        float sacc[4][4];
#pragma unroll
        for (int n = 0; n < 4; n++)
#pragma unroll
            for (int i = 0; i < 4; i++) sacc[n][i] = 0.f;

#pragma unroll
        for (int kk = 0; kk < HDIM; kk += 8) {
            const float* qr0 = &Qs[(wq + gid) * QKPAD + kk];
            const float* qr1 = &Qs[(wq + gid + 8) * QKPAD + kk];
            uint32_t a0 = __float_as_uint(qr0[tig]);
            uint32_t a1 = __float_as_uint(qr1[tig]);
            uint32_t a2 = __float_as_uint(qr0[tig + 4]);
            uint32_t a3 = __float_as_uint(qr1[tig + 4]);
#pragma unroll
            for (int n8 = 0; n8 < 4; n8++) {
                const float* kb = &Kb[(n8 * 8 + gid) * QKPAD + kk];
                uint32_t b0 = __float_as_uint(kb[tig]);
                uint32_t b1 = __float_as_uint(kb[tig + 4]);
                mma_tf32(sacc[n8], a0, a1, a2, a3, b0, b1);
            }
        }

        int qg0 = q0 + wq + gid;
        int qg1 = qg0 + 8;
        int kb0 = kt * ABC + tig * 2;
        float tm0 = -1e30f, tm1 = -1e30f;
#pragma unroll
        for (int n8 = 0; n8 < 4; n8++) {
            int c0 = kb0 + n8 * 8;
            float v0 = sacc[n8][0] * scale; if (c0 > qg0)     v0 = -1e30f;
            float v1 = sacc[n8][1] * scale; if (c0 + 1 > qg0) v1 = -1e30f;
            float v2 = sacc[n8][2] * scale; if (c0 > qg1)     v2 = -1e30f;
            float v3 = sacc[n8][3] * scale; if (c0 + 1 > qg1) v3 = -1e30f;
            sacc[n8][0] = v0; sacc[n8][1] = v1; sacc[n8][2] = v2; sacc[n8][3] = v3;
            tm0 = fmaxf(tm0, fmaxf(v0, v1));
            tm1 = fmaxf(tm1, fmaxf(v2, v3));
        }
        tm0 = fmaxf(tm0, __shfl_xor_sync(0xffffffffu, tm0, 1));
        tm0 = fmaxf(tm0, __shfl_xor_sync(0xffffffffu, tm0, 2));
        tm1 = fmaxf(tm1, __shfl_xor_sync(0xffffffffu, tm1, 1));
        tm1 = fmaxf(tm1, __shfl_xor_sync(0xffffffffu, tm1, 2));
        float mn0 = fmaxf(m0, tm0), mn1 = fmaxf(m1, tm1);
        float corr0 = __expf(m0 - mn0), corr1 = __expf(m1 - mn1);
        m0 = mn0; m1 = mn1;

        float ts0 = 0.f, ts1 = 0.f;
#pragma unroll
        for (int n8 = 0; n8 < 4; n8++) {
            float p0 = __expf(sacc[n8][0] - mn0);
            float p1 = __expf(sacc[n8][1] - mn0);
            float p2 = __expf(sacc[n8][2] - mn1);
            float p3 = __expf(sacc[n8][3] - mn1);
            ts0 += p0 + p1; ts1 += p2 + p3;
            float2 w0, w1;
            w0.x = __uint_as_float(f2tf32(p0)); w0.y = __uint_as_float(f2tf32(p1));
            w1.x = __uint_as_float(f2tf32(p2)); w1.y = __uint_as_float(f2tf32(p3));
            *reinterpret_cast<float2*>(&Ps[(wq + gid) * PPAD + n8 * 8 + tig * 2]) = w0;
            *reinterpret_cast<float2*>(&Ps[(wq + gid + 8) * PPAD + n8 * 8 + tig * 2]) = w1;
        }
        ts0 += __shfl_xor_sync(0xffffffffu, ts0, 1);
        ts0 += __shfl_xor_sync(0xffffffffu, ts0, 2);
        ts1 += __shfl_xor_sync(0xffffffffu, ts1, 1);
        ts1 += __shfl_xor_sync(0xffffffffu, ts1, 2);
        l0 = l0 * corr0 + ts0;
        l1 = l1 * corr1 + ts1;

#pragma unroll
        for (int n = 0; n < 16; n++) {
            o_acc[n][0] *= corr0; o_acc[n][1] *= corr0;
            o_acc[n][2] *= corr1; o_acc[n][3] *= corr1;
        }
        __syncwarp();

#pragma unroll
        for (int kk = 0; kk < ABC; kk += 8) {
            const float* pr0 = &Ps[(wq + gid) * PPAD + kk];
            const float* pr1 = &Ps[(wq + gid + 8) * PPAD + kk];
            uint32_t a0 = __float_as_uint(pr0[tig]);
            uint32_t a1 = __float_as_uint(pr1[tig]);
            uint32_t a2 = __float_as_uint(pr0[tig + 4]);
            uint32_t a3 = __float_as_uint(pr1[tig + 4]);
#pragma unroll
            for (int n8 = 0; n8 < 16; n8++) {
                uint32_t b0 = __float_as_uint(Vb[(kk + tig) * QKPAD + n8 * 8 + gid]);
                uint32_t b1 = __float_as_uint(Vb[(kk + tig + 4) * QKPAD + n8 * 8 + gid]);
                mma_tf32(o_acc[n8], a0, a1, a2, a3, b0, b1);
            }
        }
        __syncwarp();
        __syncthreads();
    }

    float inv0 = 1.f / l0, inv1 = 1.f / l1;
    size_t ar0 = (baserow + q0 + wq + gid) * EDIM + off;
    size_t ar1 = (baserow + q0 + wq + gid + 8) * EDIM + off;
#pragma unroll
    for (int n8 = 0; n8 < 16; n8++) {
        int col = n8 * 8 + tig * 2;
        float2 o0; o0.x = o_acc[n8][0] * inv0; o0.y = o_acc[n8][1] * inv0;
        float2 o1; o1.x = o_acc[n8][2] * inv1; o1.y = o_acc[n8][3] * inv1;
        *reinterpret_cast<float2*>(out + ar0 + col) = o0;
        *reinterpret_cast<float2*>(out + ar1 + col) = o1;
    }
}

// ---------------- loss: single-pass online log-softmax NLL (R8-exact) -------
__global__ void __launch_bounds__(256) loss_row_kernel(const float* __restrict__ logits,
                                                       const int* __restrict__ tgt,
                                                       float* __restrict__ rowloss) {
    __shared__ float shm[8], shs[8];
    int r = blockIdx.x;
    int tid = threadIdx.x, lane = tid & 31, wid = tid >> 5;
    const float* p = logits + (size_t)r * VOCAB;
    float m = -1e30f, s = 0.f;
    for (int j = tid; j < VOCAB; j += 256) {
        float vv = p[j];
        float mn = fmaxf(m, vv);
        s = s * __expf(m - mn) + __expf(vv - mn);
        m = mn;
    }
#pragma unroll
    for (int o = 16; o; o >>= 1) {
        float om = __shfl_xor_sync(0xffffffffu, m, o);
        float os = __shfl_xor_sync(0xffffffffu, s, o);
        float mn = fmaxf(m, om);
        s = s * __expf(m - mn) + os * __expf(om - mn);
        m = mn;
    }
    if (lane == 0) { shm[wid] = m; shs[wid] = s; }
    __syncthreads();
    if (tid == 0) {
        float mm = shm[0], ss = shs[0];
        for (int i = 1; i < 8; i++) {
            float mn = fmaxf(mm, shm[i]);
            ss = ss * __expf(mm - mn) + shs[i] * __expf(shm[i] - mn);
            mm = mn;
        }
        int tg = tgt[r];
        rowloss[r] = -(p[tg] - mm - logf(ss));
    }
}

__global__ void __launch_bounds__(256) loss_fin_kernel(const float* __restrict__ rl,
                                                       float* __restrict__ out) {
    __shared__ float sh[8];
    int tid = threadIdx.x, lane = tid & 31, wid = tid >> 5;
    float s = 0.f;
    for (int i = tid; i < NROWS; i += 256) s += rl[i];
#pragma unroll
    for (int o = 16; o; o >>= 1) s += __shfl_xor_sync(0xffffffffu, s, o);
    if (lane == 0) sh[wid] = s;
    __syncthreads();
    if (tid == 0) {
        float t = 0.f; for (int i = 0; i < 8; i++) t += sh[i];
        out[0] = t * (1.0f / NROWS);
    }
}

// ---------------- host orchestration ---------------------------------------
extern "C" void kernel_launch(void* const* d_in, const int* in_sizes, int n_in,
                              void* d_out, int out_size) {
    const int* idx   = (const int*)d_in[0];
    const int* tgt   = (const int*)d_in[1];
    const float* tok  = (const float*)d_in[2];
    const float* pos  = (const float*)d_in[3];
    const float* Wq   = (const float*)d_in[4];
    const float* bq   = (const float*)d_in[5];
    const float* Wk   = (const float*)d_in[6];
    const float* bk   = (const float*)d_in[7];
    const float* Wv   = (const float*)d_in[8];
    const float* bv   = (const float*)d_in[9];
    const float* Wo   = (const float*)d_in[10];
    const float* bo   = (const float*)d_in[11];
    const float* w1   = (const float*)d_in[12];
    const float* b1   = (const float*)d_in[13];
    const float* w2   = (const float*)d_in[14];
    const float* b2   = (const float*)d_in[15];
    const float* ln1s = (const float*)d_in[16];
    const float* ln1b = (const float*)d_in[17];
    const float* ln2s = (const float*)d_in[18];
    const float* ln2b = (const float*)d_in[19];
    const float* lnfs = (const float*)d_in[20];
    const float* lnfb = (const float*)d_in[21];
    const float* Wlm  = (const float*)d_in[22];
    const float* blm  = (const float*)d_in[23];
    float* out = (float*)d_out;

    float *x, *h, *q, *k, *v, *att, *mid, *rl;
    cudaGetSymbolAddress((void**)&x,   g_x);
    cudaGetSymbolAddress((void**)&h,   g_h);
    cudaGetSymbolAddress((void**)&q,   g_q);
    cudaGetSymbolAddress((void**)&k,   g_k);
    cudaGetSymbolAddress((void**)&v,   g_v);
    cudaGetSymbolAddress((void**)&att, g_att);
    cudaGetSymbolAddress((void**)&mid, g_mid);
    cudaGetSymbolAddress((void**)&rl,  g_rowloss);

    cudaFuncSetAttribute(attn_tc_kernel, cudaFuncAttributeMaxDynamicSharedMemorySize, ATTN_SMEM);
    cudaFuncSetAttribute(tgemm_kernel, cudaFuncAttributeMaxDynamicSharedMemorySize, GEMM_SMEM);
    cudaFuncSetAttribute(tgemm64_kernel, cudaFuncAttributeMaxDynamicSharedMemorySize, GEMM_SMEM64);
    cudaFuncSetAttribute(qkv_kernel, cudaFuncAttributeMaxDynamicSharedMemorySize, GEMM_SMEM);

    embed_kernel<<<NROWS, 256>>>(idx, tok, pos, x);

    dim3 gQkv(EDIM / 128, NROWS / 128, 3);
    dim3 gProj64(EDIM / 64, NROWS / 128);       // 12 x 32 = 384 CTAs
    dim3 gMlp1_64(FFDIM / 64, NROWS / 128);     // 48 x 32 = 1536 CTAs
    dim3 gLm(VOCAB / 128, NROWS / 128);
    dim3 gAttn(TLEN / ABR, NHEAD, BATCH);       // 8 x 6 x 4 = 192

    for (int l = 0; l < NLAYER; l++) {
        size_t wo = (size_t)l * EDIM * EDIM;
        size_t w1o = (size_t)l * EDIM * FFDIM;
        ln_kernel<<<NROWS, 256>>>(x, ln1s + l * EDIM, ln1b + l * EDIM, h);
        qkv_kernel<<<gQkv, 256, GEMM_SMEM>>>(h, Wq + wo, Wk + wo, Wv + wo,
                                  bq + l * EDIM, bk + l * EDIM, bv + l * EDIM, q, k, v);
        attn_tc_kernel<<<gAttn, 256, ATTN_SMEM>>>(q, k, v, att);
        tgemm64_kernel<<<gProj64, 256, GEMM_SMEM64>>>(att, Wo + wo, bo + l * EDIM, x, x, EDIM, EDIM, 1 | 4);
        ln_kernel<<<NROWS, 256>>>(x, ln2s + l * EDIM, ln2b + l * EDIM, h);
        tgemm64_kernel<<<gMlp1_64, 256, GEMM_SMEM64>>>(h, w1 + w1o, b1 + (size_t)l * FFDIM, nullptr, mid, FFDIM, EDIM, 1 | 2);
        tgemm64_kernel<<<gProj64, 256, GEMM_SMEM64>>>(mid, w2 + w1o, b2 + l * EDIM, x, x, EDIM, FFDIM, 1 | 4);
    }
    ln_kernel<<<NROWS, 256>>>(x, lnfs, lnfb, h);
    tgemm_kernel<<<gLm, 256, GEMM_SMEM>>>(h, Wlm, blm, nullptr, out, VOCAB, EDIM, 1);

    if (out_size > NROWS * VOCAB) {
        loss_row_kernel<<<NROWS, 256>>>(out, tgt, rl);
        loss_fin_kernel<<<1, 256>>>(rl, out + (size_t)NROWS * VOCAB);
    }
}

// round 13
// speedup vs baseline: 1.0737x; 1.0737x over previous
#include <cuda_runtime.h>
#include <cstdint>
#include <cstddef>

#define EDIM 768
#define TLEN 1024
#define BATCH 4
#define NHEAD 6
#define HDIM 128
#define NLAYER 6
#define VOCAB 32000
#define NROWS (BATCH*TLEN)   // 4096
#define FFDIM (4*EDIM)       // 3072

// ---------------- scratch --------------------------------------------------
__device__ float g_x[NROWS*EDIM];
__device__ float g_h[NROWS*EDIM];
__device__ float g_q[NROWS*EDIM];
__device__ float g_k[NROWS*EDIM];
__device__ float g_v[NROWS*EDIM];
__device__ float g_att[NROWS*EDIM];
__device__ float g_mid[NROWS*FFDIM];
__device__ float g_rowloss[NROWS];

__device__ __forceinline__ uint32_t f2tf32(float f) {
    uint32_t r;
    asm("cvt.rna.tf32.f32 %0, %1;" : "=r"(r) : "f"(f));
    return r;
}

// ---------------- embedding ------------------------------------------------
__global__ void embed_kernel(const int* __restrict__ idx,
                             const float* __restrict__ tok,
                             const float* __restrict__ pos,
                             float* __restrict__ x) {
    int r = blockIdx.x;
    int t = r & (TLEN - 1);
    int tk = idx[r];
    const float* te = tok + (size_t)tk * EDIM;
    const float* pe = pos + (size_t)t * EDIM;
    float* xr = x + (size_t)r * EDIM;
    for (int e = threadIdx.x; e < EDIM; e += blockDim.x)
        xr[e] = te[e] + pe[e];
}

// ---------------- layernorm ------------------------------------------------
__global__ void __launch_bounds__(256) ln_kernel(const float* __restrict__ x,
                                                 const float* __restrict__ s,
                                                 const float* __restrict__ b,
                                                 float* __restrict__ out) {
    __shared__ float sh[8];
    int r = blockIdx.x;
    int tid = threadIdx.x, lane = tid & 31, wid = tid >> 5;
    const float* xr = x + (size_t)r * EDIM;
    float v[3];
#pragma unroll
    for (int i = 0; i < 3; i++) v[i] = xr[tid + i * 256];
    float sum = v[0] + v[1] + v[2];
#pragma unroll
    for (int o = 16; o; o >>= 1) sum += __shfl_xor_sync(0xffffffffu, sum, o);
    if (lane == 0) sh[wid] = sum;
    __syncthreads();
    if (tid == 0) { float t = 0.f; for (int i = 0; i < 8; i++) t += sh[i]; sh[0] = t; }
    __syncthreads();
    float mu = sh[0] * (1.0f / EDIM);
    __syncthreads();
    float sq = 0.f;
#pragma unroll
    for (int i = 0; i < 3; i++) { float d = v[i] - mu; sq += d * d; }
#pragma unroll
    for (int o = 16; o; o >>= 1) sq += __shfl_xor_sync(0xffffffffu, sq, o);
    if (lane == 0) sh[wid] = sq;
    __syncthreads();
    if (tid == 0) { float t = 0.f; for (int i = 0; i < 8; i++) t += sh[i]; sh[0] = t; }
    __syncthreads();
    float rstd = rsqrtf(sh[0] * (1.0f / EDIM) + 1e-5f);
    float* orow = out + (size_t)r * EDIM;
#pragma unroll
    for (int i = 0; i < 3; i++) {
        int e = tid + i * 256;
        orow[e] = (v[i] - mu) * rstd * s[e] + b[e];
    }
}

// ---------------- TF32 GEMM, 4-stage cp.async pipeline (R8-exact) ----------
#define GBK 16
#define APAD 20
#define BPAD 136
#define NSTAGE 4
#define A_STG (128 * APAD)
#define B_STG (GBK * BPAD)
#define GEMM_SMEM (NSTAGE * (A_STG + B_STG) * (int)sizeof(float))

__device__ __forceinline__ void cp16(void* dst, const void* src) {
    uint32_t d = (uint32_t)__cvta_generic_to_shared(dst);
    asm volatile("cp.async.cg.shared.global [%0], [%1], 16;" :: "r"(d), "l"(src));
}

__device__ __forceinline__ void mma_tf32(float c[4],
                                         uint32_t a0, uint32_t a1, uint32_t a2, uint32_t a3,
                                         uint32_t b0, uint32_t b1) {
    asm volatile(
        "mma.sync.aligned.m16n8k8.row.col.f32.tf32.tf32.f32 "
        "{%0,%1,%2,%3}, {%4,%5,%6,%7}, {%8,%9}, {%0,%1,%2,%3};\n"
        : "+f"(c[0]), "+f"(c[1]), "+f"(c[2]), "+f"(c[3])
        : "r"(a0), "r"(a1), "r"(a2), "r"(a3), "r"(b0), "r"(b1));
}

// flags: 1=bias, 2=relu, 4=residual-add, 8=tf32-round output
__device__ __forceinline__ void gemm_core(
    const float* __restrict__ A, const float* __restrict__ Bm,
    const float* __restrict__ bias, const float* __restrict__ res,
    float* __restrict__ C, int N, int K, int flags, int bx, int by) {
    extern __shared__ float smem_dyn[];
    float* AsAll = smem_dyn;
    float* BsAll = smem_dyn + NSTAGE * A_STG;

    int tid = threadIdx.x;
    int lane = tid & 31, wid = tid >> 5;
    int wm = (wid & 1) * 64;
    int wn = (wid >> 1) * 32;
    int gid = lane >> 2;
    int tig = lane & 3;

    const float* Ab = A + (size_t)(by * 128) * K;
    const float* Bb = Bm + bx * 128;

    int aR0 = tid >> 2;
    int aC0 = (tid & 3) * 4;
    int bR0 = tid >> 5;
    int bC0 = (tid & 31) * 4;

    float c[4][4][4];
#pragma unroll
    for (int mt = 0; mt < 4; mt++)
#pragma unroll
        for (int nt = 0; nt < 4; nt++)
#pragma unroll
            for (int i = 0; i < 4; i++) c[mt][nt][i] = 0.f;

    int nIter = K / GBK;

#pragma unroll
    for (int s = 0; s < NSTAGE - 1; s++) {
        if (s < nIter) {
            int k0 = s * GBK;
            float* As = AsAll + s * A_STG;
            float* Bs = BsAll + s * B_STG;
            cp16(&As[aR0 * APAD + aC0], Ab + (size_t)aR0 * K + k0 + aC0);
            cp16(&As[(aR0 + 64) * APAD + aC0], Ab + (size_t)(aR0 + 64) * K + k0 + aC0);
            cp16(&Bs[bR0 * BPAD + bC0], Bb + (size_t)(k0 + bR0) * N + bC0);
            cp16(&Bs[(bR0 + 8) * BPAD + bC0], Bb + (size_t)(k0 + bR0 + 8) * N + bC0);
        }
        asm volatile("cp.async.commit_group;");
    }

    for (int i = 0; i < nIter; i++) {
        if (i + NSTAGE - 1 < nIter) {
            int k0 = (i + NSTAGE - 1) * GBK;
            int s = (i + NSTAGE - 1) & (NSTAGE - 1);
            float* As = AsAll + s * A_STG;
            float* Bs = BsAll + s * B_STG;
            cp16(&As[aR0 * APAD + aC0], Ab + (size_t)aR0 * K + k0 + aC0);
            cp16(&As[(aR0 + 64) * APAD + aC0], Ab + (size_t)(aR0 + 64) * K + k0 + aC0);
            cp16(&Bs[bR0 * BPAD + bC0], Bb + (size_t)(k0 + bR0) * N + bC0);
            cp16(&Bs[(bR0 + 8) * BPAD + bC0], Bb + (size_t)(k0 + bR0 + 8) * N + bC0);
        }
        asm volatile("cp.async.commit_group;");
        asm volatile("cp.async.wait_group %0;" :: "n"(NSTAGE - 1));
        __syncthreads();

        int cur = i & (NSTAGE - 1);
        const float* As = AsAll + cur * A_STG;
        const float* Bs = BsAll + cur * B_STG;

#pragma unroll
        for (int kk = 0; kk < GBK; kk += 8) {
            uint32_t af[4][4];
#pragma unroll
            for (int mt = 0; mt < 4; mt++) {
                int rb = (wm + mt * 16 + gid) * APAD;
                af[mt][0] = f2tf32(As[rb + kk + tig]);
                af[mt][1] = f2tf32(As[rb + 8 * APAD + kk + tig]);
                af[mt][2] = f2tf32(As[rb + kk + tig + 4]);
                af[mt][3] = f2tf32(As[rb + 8 * APAD + kk + tig + 4]);
            }
            uint32_t bf[4][2];
#pragma unroll
            for (int nt = 0; nt < 4; nt++) {
                int cb = wn + nt * 8 + gid;
                bf[nt][0] = f2tf32(Bs[(kk + tig) * BPAD + cb]);
                bf[nt][1] = f2tf32(Bs[(kk + tig + 4) * BPAD + cb]);
            }
#pragma unroll
            for (int mt = 0; mt < 4; mt++)
#pragma unroll
                for (int nt = 0; nt < 4; nt++)
                    mma_tf32(c[mt][nt], af[mt][0], af[mt][1], af[mt][2], af[mt][3],
                             bf[nt][0], bf[nt][1]);
        }
        __syncthreads();
    }

#pragma unroll
    for (int mt = 0; mt < 4; mt++) {
#pragma unroll
        for (int nt = 0; nt < 4; nt++) {
            int row0 = by * 128 + wm + mt * 16 + gid;
            int col = bx * 128 + wn + nt * 8 + tig * 2;
            float2 bb = make_float2(0.f, 0.f);
            if (flags & 1) bb = *reinterpret_cast<const float2*>(bias + col);
#pragma unroll
            for (int half = 0; half < 2; half++) {
                int row = row0 + half * 8;
                float v0 = c[mt][nt][half * 2 + 0] + bb.x;
                float v1 = c[mt][nt][half * 2 + 1] + bb.y;
                if (flags & 2) { v0 = fmaxf(v0, 0.f); v1 = fmaxf(v1, 0.f); }
                size_t base = (size_t)row * N + col;
                if (flags & 4) {
                    float2 rr = *reinterpret_cast<const float2*>(res + base);
                    v0 += rr.x; v1 += rr.y;
                }
                if (flags & 8) {
                    v0 = __uint_as_float(f2tf32(v0));
                    v1 = __uint_as_float(f2tf32(v1));
                }
                float2 o2; o2.x = v0; o2.y = v1;
                *reinterpret_cast<float2*>(C + base) = o2;
            }
        }
    }
}

__global__ void __launch_bounds__(256) tgemm_kernel(
    const float* __restrict__ A, const float* __restrict__ Bm,
    const float* __restrict__ bias, const float* __restrict__ res,
    float* __restrict__ C, int N, int K, int flags) {
    gemm_core(A, Bm, bias, res, C, N, K, flags, blockIdx.x, blockIdx.y);
}

// M-tile on blockIdx.x (fast-varying) -> one wave covers all M-tiles for few
// N-tiles: Wlm streams from DRAM once instead of ~32x on the LM head.
__global__ void __launch_bounds__(256) tgemm_swap_kernel(
    const float* __restrict__ A, const float* __restrict__ Bm,
    const float* __restrict__ bias, const float* __restrict__ res,
    float* __restrict__ C, int N, int K, int flags) {
    gemm_core(A, Bm, bias, res, C, N, K, flags, blockIdx.y, blockIdx.x);
}

__global__ void __launch_bounds__(256) qkv_kernel(
    const float* __restrict__ h,
    const float* __restrict__ Wq, const float* __restrict__ Wk, const float* __restrict__ Wv,
    const float* __restrict__ bq, const float* __restrict__ bk, const float* __restrict__ bv,
    float* __restrict__ q, float* __restrict__ k, float* __restrict__ v) {
    const float* W; const float* bb; float* o;
    if (blockIdx.z == 0)      { W = Wq; bb = bq; o = q; }
    else if (blockIdx.z == 1) { W = Wk; bb = bk; o = k; }
    else                      { W = Wv; bb = bv; o = v; }
    gemm_core(h, W, bb, nullptr, o, EDIM, EDIM, 1 | 8, blockIdx.x, blockIdx.y);
}

// ---------------- tf32 flash attention (R8-exact) ---------------------------
#define ABR 128
#define ABC 32
#define QKPAD 132
#define PPAD 36
#define ATTN_SMEM ((ABR*QKPAD + 4*ABC*QKPAD + ABR*PPAD) * (int)sizeof(float))

__global__ void __launch_bounds__(256) attn_tc_kernel(const float* __restrict__ q,
                                                      const float* __restrict__ k,
                                                      const float* __restrict__ v,
                                                      float* __restrict__ out) {
    extern __shared__ float dyn[];
    float* Qs = dyn;
    float* Ksb = Qs + ABR * QKPAD;
    float* Vsb = Ksb + 2 * ABC * QKPAD;
    float* Ps = Vsb + 2 * ABC * QKPAD;

    int qb = blockIdx.x, h = blockIdx.y, b = blockIdx.z;
    int tid = threadIdx.x, lane = tid & 31, wid = tid >> 5;
    int gid = lane >> 2, tig = lane & 3;
    int wq = wid * 16;
    int q0 = qb * ABR;
    size_t baserow = (size_t)b * TLEN;
    int off = h * HDIM;
    const float scale = 0.08838834764831845f;

    for (int f = tid; f < ABR * 32; f += 256) {
        int r = f >> 5, c4 = (f & 31) * 4;
        float4 t = *reinterpret_cast<const float4*>(q + (baserow + q0 + r) * EDIM + off + c4);
        float* dst = &Qs[r * QKPAD + c4];
        dst[0] = t.x; dst[1] = t.y; dst[2] = t.z; dst[3] = t.w;
    }

    float o_acc[16][4];
#pragma unroll
    for (int n = 0; n < 16; n++)
#pragma unroll
        for (int i = 0; i < 4; i++) o_acc[n][i] = 0.f;
    float m0 = -1e30f, m1 = -1e30f, l0 = 0.f, l1 = 0.f;

    int ntile = 4 * qb + 4;

    {
        for (int f = tid; f < ABC * 32; f += 256) {
            int r = f >> 5, c4 = (f & 31) * 4;
            size_t g = (baserow + r) * EDIM + off + c4;
            cp16(&Ksb[r * QKPAD + c4], k + g);
            cp16(&Vsb[r * QKPAD + c4], v + g);
        }
        asm volatile("cp.async.commit_group;");
    }

    for (int kt = 0; kt < ntile; kt++) {
        int cur = kt & 1;
        if (kt + 1 < ntile) {
            int nxt = cur ^ 1;
            float* Kd = Ksb + nxt * ABC * QKPAD;
            float* Vd = Vsb + nxt * ABC * QKPAD;
            for (int f = tid; f < ABC * 32; f += 256) {
                int r = f >> 5, c4 = (f & 31) * 4;
                size_t g = (baserow + (kt + 1) * ABC + r) * EDIM + off + c4;
                cp16(&Kd[r * QKPAD + c4], k + g);
                cp16(&Vd[r * QKPAD + c4], v + g);
            }
            asm volatile("cp.async.commit_group;");
            asm volatile("cp.async.wait_group 1;");
        } else {
            asm volatile("cp.async.wait_group 0;");
        }
        __syncthreads();

        const float* Kb = Ksb + cur * ABC * QKPAD;
        const float* Vb = Vsb + cur * ABC * QKPAD;

        float sacc[4][4];
#pragma unroll
        for (int n = 0; n < 4; n++)
#pragma unroll
            for (int i = 0; i < 4; i++) sacc[n][i] = 0.f;

#pragma unroll
        for (int kk = 0; kk < HDIM; kk += 8) {
            const float* qr0 = &Qs[(wq + gid) * QKPAD + kk];
            const float* qr1 = &Qs[(wq + gid + 8) * QKPAD + kk];
            uint32_t a0 = __float_as_uint(qr0[tig]);
            uint32_t a1 = __float_as_uint(qr1[tig]);
            uint32_t a2 = __float_as_uint(qr0[tig + 4]);
            uint32_t a3 = __float_as_uint(qr1[tig + 4]);
#pragma unroll
            for (int n8 = 0; n8 < 4; n8++) {
                const float* kb = &Kb[(n8 * 8 + gid) * QKPAD + kk];
                uint32_t b0 = __float_as_uint(kb[tig]);
                uint32_t b1 = __float_as_uint(kb[tig + 4]);
                mma_tf32(sacc[n8], a0, a1, a2, a3, b0, b1);
            }
        }

        int qg0 = q0 + wq + gid;
        int qg1 = qg0 + 8;
        int kb0 = kt * ABC + tig * 2;
        float tm0 = -1e30f, tm1 = -1e30f;
#pragma unroll
        for (int n8 = 0; n8 < 4; n8++) {
            int c0 = kb0 + n8 * 8;
            float v0 = sacc[n8][0] * scale; if (c0 > qg0)     v0 = -1e30f;
            float v1 = sacc[n8][1] * scale; if (c0 + 1 > qg0) v1 = -1e30f;
            float v2 = sacc[n8][2] * scale; if (c0 > qg1)     v2 = -1e30f;
            float v3 = sacc[n8][3] * scale; if (c0 + 1 > qg1) v3 = -1e30f;
            sacc[n8][0] = v0; sacc[n8][1] = v1; sacc[n8][2] = v2; sacc[n8][3] = v3;
            tm0 = fmaxf(tm0, fmaxf(v0, v1));
            tm1 = fmaxf(tm1, fmaxf(v2, v3));
        }
        tm0 = fmaxf(tm0, __shfl_xor_sync(0xffffffffu, tm0, 1));
        tm0 = fmaxf(tm0, __shfl_xor_sync(0xffffffffu, tm0, 2));
        tm1 = fmaxf(tm1, __shfl_xor_sync(0xffffffffu, tm1, 1));
        tm1 = fmaxf(tm1, __shfl_xor_sync(0xffffffffu, tm1, 2));
        float mn0 = fmaxf(m0, tm0), mn1 = fmaxf(m1, tm1);
        float corr0 = __expf(m0 - mn0), corr1 = __expf(m1 - mn1);
        m0 = mn0; m1 = mn1;

        float ts0 = 0.f, ts1 = 0.f;
#pragma unroll
        for (int n8 = 0; n8 < 4; n8++) {
            float p0 = __expf(sacc[n8][0] - mn0);
            float p1 = __expf(sacc[n8][1] - mn0);
            float p2 = __expf(sacc[n8][2] - mn1);
            float p3 = __expf(sacc[n8][3] - mn1);
            ts0 += p0 + p1; ts1 += p2 + p3;
            float2 w0, w1;
            w0.x = __uint_as_float(f2tf32(p0)); w0.y = __uint_as_float(f2tf32(p1));
            w1.x = __uint_as_float(f2tf32(p2)); w1.y = __uint_as_float(f2tf32(p3));
            *reinterpret_cast<float2*>(&Ps[(wq + gid) * PPAD + n8 * 8 + tig * 2]) = w0;
            *reinterpret_cast<float2*>(&Ps[(wq + gid + 8) * PPAD + n8 * 8 + tig * 2]) = w1;
        }
        ts0 += __shfl_xor_sync(0xffffffffu, ts0, 1);
        ts0 += __shfl_xor_sync(0xffffffffu, ts0, 2);
        ts1 += __shfl_xor_sync(0xffffffffu, ts1, 1);
        ts1 += __shfl_xor_sync(0xffffffffu, ts1, 2);
        l0 = l0 * corr0 + ts0;
        l1 = l1 * corr1 + ts1;

#pragma unroll
        for (int n = 0; n < 16; n++) {
            o_acc[n][0] *= corr0; o_acc[n][1] *= corr0;
            o_acc[n][2] *= corr1; o_acc[n][3] *= corr1;
        }
        __syncwarp();

#pragma unroll
        for (int kk = 0; kk < ABC; kk += 8) {
            const float* pr0 = &Ps[(wq + gid) * PPAD + kk];
            const float* pr1 = &Ps[(wq + gid + 8) * PPAD + kk];
            uint32_t a0 = __float_as_uint(pr0[tig]);
            uint32_t a1 = __float_as_uint(pr1[tig]);
            uint32_t a2 = __float_as_uint(pr0[tig + 4]);
            uint32_t a3 = __float_as_uint(pr1[tig + 4]);
#pragma unroll
            for (int n8 = 0; n8 < 16; n8++) {
                uint32_t b0 = __float_as_uint(Vb[(kk + tig) * QKPAD + n8 * 8 + gid]);
                uint32_t b1 = __float_as_uint(Vb[(kk + tig + 4) * QKPAD + n8 * 8 + gid]);
                mma_tf32(o_acc[n8], a0, a1, a2, a3, b0, b1);
            }
        }
        __syncwarp();
        __syncthreads();
    }

    float inv0 = 1.f / l0, inv1 = 1.f / l1;
    size_t ar0 = (baserow + q0 + wq + gid) * EDIM + off;
    size_t ar1 = (baserow + q0 + wq + gid + 8) * EDIM + off;
#pragma unroll
    for (int n8 = 0; n8 < 16; n8++) {
        int col = n8 * 8 + tig * 2;
        float2 o0; o0.x = o_acc[n8][0] * inv0; o0.y = o_acc[n8][1] * inv0;
        float2 o1; o1.x = o_acc[n8][2] * inv1; o1.y = o_acc[n8][3] * inv1;
        *reinterpret_cast<float2*>(out + ar0 + col) = o0;
        *reinterpret_cast<float2*>(out + ar1 + col) = o1;
    }
}

// ---------------- loss: single-pass online log-softmax NLL (R8-exact) -------
__global__ void __launch_bounds__(256) loss_row_kernel(const float* __restrict__ logits,
                                                       const int* __restrict__ tgt,
                                                       float* __restrict__ rowloss) {
    __shared__ float shm[8], shs[8];
    int r = blockIdx.x;
    int tid = threadIdx.x, lane = tid & 31, wid = tid >> 5;
    const float* p = logits + (size_t)r * VOCAB;
    float m = -1e30f, s = 0.f;
    for (int j = tid; j < VOCAB; j += 256) {
        float vv = p[j];
        float mn = fmaxf(m, vv);
        s = s * __expf(m - mn) + __expf(vv - mn);
        m = mn;
    }
#pragma unroll
    for (int o = 16; o; o >>= 1) {
        float om = __shfl_xor_sync(0xffffffffu, m, o);
        float os = __shfl_xor_sync(0xffffffffu, s, o);
        float mn = fmaxf(m, om);
        s = s * __expf(m - mn) + os * __expf(om - mn);
        m = mn;
    }
    if (lane == 0) { shm[wid] = m; shs[wid] = s; }
    __syncthreads();
    if (tid == 0) {
        float mm = shm[0], ss = shs[0];
        for (int i = 1; i < 8; i++) {
            float mn = fmaxf(mm, shm[i]);
            ss = ss * __expf(mm - mn) + shs[i] * __expf(shm[i] - mn);
            mm = mn;
        }
        int tg = tgt[r];
        rowloss[r] = -(p[tg] - mm - logf(ss));
    }
}

__global__ void __launch_bounds__(256) loss_fin_kernel(const float* __restrict__ rl,
                                                       float* __restrict__ out) {
    __shared__ float sh[8];
    int tid = threadIdx.x, lane = tid & 31, wid = tid >> 5;
    float s = 0.f;
    for (int i = tid; i < NROWS; i += 256) s += rl[i];
#pragma unroll
    for (int o = 16; o; o >>= 1) s += __shfl_xor_sync(0xffffffffu, s, o);
    if (lane == 0) sh[wid] = s;
    __syncthreads();
    if (tid == 0) {
        float t = 0.f; for (int i = 0; i < 8; i++) t += sh[i];
        out[0] = t * (1.0f / NROWS);
    }
}

// ---------------- host orchestration ---------------------------------------
extern "C" void kernel_launch(void* const* d_in, const int* in_sizes, int n_in,
                              void* d_out, int out_size) {
    const int* idx   = (const int*)d_in[0];
    const int* tgt   = (const int*)d_in[1];
    const float* tok  = (const float*)d_in[2];
    const float* pos  = (const float*)d_in[3];
    const float* Wq   = (const float*)d_in[4];
    const float* bq   = (const float*)d_in[5];
    const float* Wk   = (const float*)d_in[6];
    const float* bk   = (const float*)d_in[7];
    const float* Wv   = (const float*)d_in[8];
    const float* bv   = (const float*)d_in[9];
    const float* Wo   = (const float*)d_in[10];
    const float* bo   = (const float*)d_in[11];
    const float* w1   = (const float*)d_in[12];
    const float* b1   = (const float*)d_in[13];
    const float* w2   = (const float*)d_in[14];
    const float* b2   = (const float*)d_in[15];
    const float* ln1s = (const float*)d_in[16];
    const float* ln1b = (const float*)d_in[17];
    const float* ln2s = (const float*)d_in[18];
    const float* ln2b = (const float*)d_in[19];
    const float* lnfs = (const float*)d_in[20];
    const float* lnfb = (const float*)d_in[21];
    const float* Wlm  = (const float*)d_in[22];
    const float* blm  = (const float*)d_in[23];
    float* out = (float*)d_out;

    float *x, *h, *q, *k, *v, *att, *mid, *rl;
    cudaGetSymbolAddress((void**)&x,   g_x);
    cudaGetSymbolAddress((void**)&h,   g_h);
    cudaGetSymbolAddress((void**)&q,   g_q);
    cudaGetSymbolAddress((void**)&k,   g_k);
    cudaGetSymbolAddress((void**)&v,   g_v);
    cudaGetSymbolAddress((void**)&att, g_att);
    cudaGetSymbolAddress((void**)&mid, g_mid);
    cudaGetSymbolAddress((void**)&rl,  g_rowloss);

    cudaFuncSetAttribute(attn_tc_kernel, cudaFuncAttributeMaxDynamicSharedMemorySize, ATTN_SMEM);
    cudaFuncSetAttribute(tgemm_kernel, cudaFuncAttributeMaxDynamicSharedMemorySize, GEMM_SMEM);
    cudaFuncSetAttribute(tgemm_swap_kernel, cudaFuncAttributeMaxDynamicSharedMemorySize, GEMM_SMEM);
    cudaFuncSetAttribute(qkv_kernel, cudaFuncAttributeMaxDynamicSharedMemorySize, GEMM_SMEM);

    embed_kernel<<<NROWS, 256>>>(idx, tok, pos, x);

    dim3 gProj(EDIM / 128, NROWS / 128);
    dim3 gQkv(EDIM / 128, NROWS / 128, 3);
    dim3 gMlp1(FFDIM / 128, NROWS / 128);
    dim3 gLmSwap(NROWS / 128, VOCAB / 128);   // M fastest -> Wlm read once from DRAM
    dim3 gAttn(TLEN / ABR, NHEAD, BATCH);     // 8 x 6 x 4 = 192

    for (int l = 0; l < NLAYER; l++) {
        size_t wo = (size_t)l * EDIM * EDIM;
        size_t w1o = (size_t)l * EDIM * FFDIM;
        ln_kernel<<<NROWS, 256>>>(x, ln1s + l * EDIM, ln1b + l * EDIM, h);
        qkv_kernel<<<gQkv, 256, GEMM_SMEM>>>(h, Wq + wo, Wk + wo, Wv + wo,
                                  bq + l * EDIM, bk + l * EDIM, bv + l * EDIM, q, k, v);
        attn_tc_kernel<<<gAttn, 256, ATTN_SMEM>>>(q, k, v, att);
        tgemm_kernel<<<gProj, 256, GEMM_SMEM>>>(att, Wo + wo, bo + l * EDIM, x, x, EDIM, EDIM, 1 | 4);
        ln_kernel<<<NROWS, 256>>>(x, ln2s + l * EDIM, ln2b + l * EDIM, h);
        tgemm_kernel<<<gMlp1, 256, GEMM_SMEM>>>(h, w1 + w1o, b1 + (size_t)l * FFDIM, nullptr, mid, FFDIM, EDIM, 1 | 2);
        tgemm_kernel<<<gProj, 256, GEMM_SMEM>>>(mid, w2 + w1o, b2 + l * EDIM, x, x, EDIM, FFDIM, 1 | 4);
    }
    ln_kernel<<<NROWS, 256>>>(x, lnfs, lnfb, h);
    tgemm_swap_kernel<<<gLmSwap, 256, GEMM_SMEM>>>(h, Wlm, blm, nullptr, out, VOCAB, EDIM, 1);

    if (out_size > NROWS * VOCAB) {
        loss_row_kernel<<<NROWS, 256>>>(out, tgt, rl);
        loss_fin_kernel<<<1, 256>>>(rl, out + (size_t)NROWS * VOCAB);
    }
}

// round 14
// speedup vs baseline: 1.1159x; 1.0392x over previous
#include <cuda_runtime.h>
#include <cstdint>
#include <cstddef>

#define EDIM 768
#define TLEN 1024
#define BATCH 4
#define NHEAD 6
#define HDIM 128
#define NLAYER 6
#define VOCAB 32000
#define NROWS (BATCH*TLEN)   // 4096
#define FFDIM (4*EDIM)       // 3072

// ---------------- scratch --------------------------------------------------
__device__ float g_x[NROWS*EDIM];
__device__ float g_h[NROWS*EDIM];
__device__ float g_q[NROWS*EDIM];
__device__ float g_k[NROWS*EDIM];
__device__ float g_v[NROWS*EDIM];
__device__ float g_att[NROWS*EDIM];
__device__ float g_mid[NROWS*FFDIM];
__device__ float g_rowloss[NROWS];

__device__ __forceinline__ uint32_t f2tf32(float f) {
    uint32_t r;
    asm("cvt.rna.tf32.f32 %0, %1;" : "=r"(r) : "f"(f));
    return r;
}

// ---------------- embedding ------------------------------------------------
__global__ void embed_kernel(const int* __restrict__ idx,
                             const float* __restrict__ tok,
                             const float* __restrict__ pos,
                             float* __restrict__ x) {
    int r = blockIdx.x;
    int t = r & (TLEN - 1);
    int tk = idx[r];
    const float* te = tok + (size_t)tk * EDIM;
    const float* pe = pos + (size_t)t * EDIM;
    float* xr = x + (size_t)r * EDIM;
    for (int e = threadIdx.x; e < EDIM; e += blockDim.x)
        xr[e] = te[e] + pe[e];
}

// ---------------- layernorm ------------------------------------------------
__global__ void __launch_bounds__(256) ln_kernel(const float* __restrict__ x,
                                                 const float* __restrict__ s,
                                                 const float* __restrict__ b,
                                                 float* __restrict__ out) {
    __shared__ float sh[8];
    int r = blockIdx.x;
    int tid = threadIdx.x, lane = tid & 31, wid = tid >> 5;
    const float* xr = x + (size_t)r * EDIM;
    float v[3];
#pragma unroll
    for (int i = 0; i < 3; i++) v[i] = xr[tid + i * 256];
    float sum = v[0] + v[1] + v[2];
#pragma unroll
    for (int o = 16; o; o >>= 1) sum += __shfl_xor_sync(0xffffffffu, sum, o);
    if (lane == 0) sh[wid] = sum;
    __syncthreads();
    if (tid == 0) { float t = 0.f; for (int i = 0; i < 8; i++) t += sh[i]; sh[0] = t; }
    __syncthreads();
    float mu = sh[0] * (1.0f / EDIM);
    __syncthreads();
    float sq = 0.f;
#pragma unroll
    for (int i = 0; i < 3; i++) { float d = v[i] - mu; sq += d * d; }
#pragma unroll
    for (int o = 16; o; o >>= 1) sq += __shfl_xor_sync(0xffffffffu, sq, o);
    if (lane == 0) sh[wid] = sq;
    __syncthreads();
    if (tid == 0) { float t = 0.f; for (int i = 0; i < 8; i++) t += sh[i]; sh[0] = t; }
    __syncthreads();
    float rstd = rsqrtf(sh[0] * (1.0f / EDIM) + 1e-5f);
    float* orow = out + (size_t)r * EDIM;
#pragma unroll
    for (int i = 0; i < 3; i++) {
        int e = tid + i * 256;
        orow[e] = (v[i] - mu) * rstd * s[e] + b[e];
    }
}

// ---------------- TF32 GEMM, 4-stage cp.async pipeline (R8-exact) ----------
#define GBK 16
#define APAD 20
#define BPAD 136
#define NSTAGE 4
#define A_STG (128 * APAD)
#define B_STG (GBK * BPAD)
#define GEMM_SMEM (NSTAGE * (A_STG + B_STG) * (int)sizeof(float))

__device__ __forceinline__ void cp16(void* dst, const void* src) {
    uint32_t d = (uint32_t)__cvta_generic_to_shared(dst);
    asm volatile("cp.async.cg.shared.global [%0], [%1], 16;" :: "r"(d), "l"(src));
}

__device__ __forceinline__ void mma_tf32(float c[4],
                                         uint32_t a0, uint32_t a1, uint32_t a2, uint32_t a3,
                                         uint32_t b0, uint32_t b1) {
    asm volatile(
        "mma.sync.aligned.m16n8k8.row.col.f32.tf32.tf32.f32 "
        "{%0,%1,%2,%3}, {%4,%5,%6,%7}, {%8,%9}, {%0,%1,%2,%3};\n"
        : "+f"(c[0]), "+f"(c[1]), "+f"(c[2]), "+f"(c[3])
        : "r"(a0), "r"(a1), "r"(a2), "r"(a3), "r"(b0), "r"(b1));
}

// flags: 1=bias, 2=relu, 4=residual-add, 8=tf32-round output
__device__ __forceinline__ void gemm_core(
    const float* __restrict__ A, const float* __restrict__ Bm,
    const float* __restrict__ bias, const float* __restrict__ res,
    float* __restrict__ C, int N, int K, int flags, int bx, int by) {
    extern __shared__ float smem_dyn[];
    float* AsAll = smem_dyn;
    float* BsAll = smem_dyn + NSTAGE * A_STG;

    int tid = threadIdx.x;
    int lane = tid & 31, wid = tid >> 5;
    int wm = (wid & 1) * 64;
    int wn = (wid >> 1) * 32;
    int gid = lane >> 2;
    int tig = lane & 3;

    const float* Ab = A + (size_t)(by * 128) * K;
    const float* Bb = Bm + bx * 128;

    int aR0 = tid >> 2;
    int aC0 = (tid & 3) * 4;
    int bR0 = tid >> 5;
    int bC0 = (tid & 31) * 4;

    float c[4][4][4];
#pragma unroll
    for (int mt = 0; mt < 4; mt++)
#pragma unroll
        for (int nt = 0; nt < 4; nt++)
#pragma unroll
            for (int i = 0; i < 4; i++) c[mt][nt][i] = 0.f;

    int nIter = K / GBK;

#pragma unroll
    for (int s = 0; s < NSTAGE - 1; s++) {
        if (s < nIter) {
            int k0 = s * GBK;
            float* As = AsAll + s * A_STG;
            float* Bs = BsAll + s * B_STG;
            cp16(&As[aR0 * APAD + aC0], Ab + (size_t)aR0 * K + k0 + aC0);
            cp16(&As[(aR0 + 64) * APAD + aC0], Ab + (size_t)(aR0 + 64) * K + k0 + aC0);
            cp16(&Bs[bR0 * BPAD + bC0], Bb + (size_t)(k0 + bR0) * N + bC0);
            cp16(&Bs[(bR0 + 8) * BPAD + bC0], Bb + (size_t)(k0 + bR0 + 8) * N + bC0);
        }
        asm volatile("cp.async.commit_group;");
    }

    for (int i = 0; i < nIter; i++) {
        if (i + NSTAGE - 1 < nIter) {
            int k0 = (i + NSTAGE - 1) * GBK;
            int s = (i + NSTAGE - 1) & (NSTAGE - 1);
            float* As = AsAll + s * A_STG;
            float* Bs = BsAll + s * B_STG;
            cp16(&As[aR0 * APAD + aC0], Ab + (size_t)aR0 * K + k0 + aC0);
            cp16(&As[(aR0 + 64) * APAD + aC0], Ab + (size_t)(aR0 + 64) * K + k0 + aC0);
            cp16(&Bs[bR0 * BPAD + bC0], Bb + (size_t)(k0 + bR0) * N + bC0);
            cp16(&Bs[(bR0 + 8) * BPAD + bC0], Bb + (size_t)(k0 + bR0 + 8) * N + bC0);
        }
        asm volatile("cp.async.commit_group;");
        asm volatile("cp.async.wait_group %0;" :: "n"(NSTAGE - 1));
        __syncthreads();

        int cur = i & (NSTAGE - 1);
        const float* As = AsAll + cur * A_STG;
        const float* Bs = BsAll + cur * B_STG;

#pragma unroll
        for (int kk = 0; kk < GBK; kk += 8) {
            uint32_t af[4][4];
#pragma unroll
            for (int mt = 0; mt < 4; mt++) {
                int rb = (wm + mt * 16 + gid) * APAD;
                af[mt][0] = f2tf32(As[rb + kk + tig]);
                af[mt][1] = f2tf32(As[rb + 8 * APAD + kk + tig]);
                af[mt][2] = f2tf32(As[rb + kk + tig + 4]);
                af[mt][3] = f2tf32(As[rb + 8 * APAD + kk + tig + 4]);
            }
            uint32_t bf[4][2];
#pragma unroll
            for (int nt = 0; nt < 4; nt++) {
                int cb = wn + nt * 8 + gid;
                bf[nt][0] = f2tf32(Bs[(kk + tig) * BPAD + cb]);
                bf[nt][1] = f2tf32(Bs[(kk + tig + 4) * BPAD + cb]);
            }
#pragma unroll
            for (int mt = 0; mt < 4; mt++)
#pragma unroll
                for (int nt = 0; nt < 4; nt++)
                    mma_tf32(c[mt][nt], af[mt][0], af[mt][1], af[mt][2], af[mt][3],
                             bf[nt][0], bf[nt][1]);
        }
        __syncthreads();
    }

#pragma unroll
    for (int mt = 0; mt < 4; mt++) {
#pragma unroll
        for (int nt = 0; nt < 4; nt++) {
            int row0 = by * 128 + wm + mt * 16 + gid;
            int col = bx * 128 + wn + nt * 8 + tig * 2;
            float2 bb = make_float2(0.f, 0.f);
            if (flags & 1) bb = *reinterpret_cast<const float2*>(bias + col);
#pragma unroll
            for (int half = 0; half < 2; half++) {
                int row = row0 + half * 8;
                float v0 = c[mt][nt][half * 2 + 0] + bb.x;
                float v1 = c[mt][nt][half * 2 + 1] + bb.y;
                if (flags & 2) { v0 = fmaxf(v0, 0.f); v1 = fmaxf(v1, 0.f); }
                size_t base = (size_t)row * N + col;
                if (flags & 4) {
                    float2 rr = *reinterpret_cast<const float2*>(res + base);
                    v0 += rr.x; v1 += rr.y;
                }
                if (flags & 8) {
                    v0 = __uint_as_float(f2tf32(v0));
                    v1 = __uint_as_float(f2tf32(v1));
                }
                float2 o2; o2.x = v0; o2.y = v1;
                *reinterpret_cast<float2*>(C + base) = o2;
            }
        }
    }
}

__global__ void __launch_bounds__(256) tgemm_kernel(
    const float* __restrict__ A, const float* __restrict__ Bm,
    const float* __restrict__ bias, const float* __restrict__ res,
    float* __restrict__ C, int N, int K, int flags) {
    gemm_core(A, Bm, bias, res, C, N, K, flags, blockIdx.x, blockIdx.y);
}

__global__ void __launch_bounds__(256) qkv_kernel(
    const float* __restrict__ h,
    const float* __restrict__ Wq, const float* __restrict__ Wk, const float* __restrict__ Wv,
    const float* __restrict__ bq, const float* __restrict__ bk, const float* __restrict__ bv,
    float* __restrict__ q, float* __restrict__ k, float* __restrict__ v) {
    const float* W; const float* bb; float* o;
    if (blockIdx.z == 0)      { W = Wq; bb = bq; o = q; }
    else if (blockIdx.z == 1) { W = Wk; bb = bk; o = k; }
    else                      { W = Wv; bb = bv; o = v; }
    gemm_core(h, W, bb, nullptr, o, EDIM, EDIM, 1 | 8, blockIdx.x, blockIdx.y);
}

// ---------------- tf32 flash attention (R8 math; heavy-CTA-first grid) ------
// Grid: x = b*NHEAD + h (24, fastest), y = qb slot (8, slowest). qb = 7 - y so
// the 32-tile CTAs get the LOWEST block ids -> scheduled in wave 1; the 44
// wave-2 CTAs are all light (qb 0/1). LPT-style makespan ~33 tile-units vs ~48.
#define ABR 128
#define ABC 32
#define QKPAD 132
#define PPAD 36
#define ATTN_SMEM ((ABR*QKPAD + 4*ABC*QKPAD + ABR*PPAD) * (int)sizeof(float))

__global__ void __launch_bounds__(256) attn_tc_kernel(const float* __restrict__ q,
                                                      const float* __restrict__ k,
                                                      const float* __restrict__ v,
                                                      float* __restrict__ out) {
    extern __shared__ float dyn[];
    float* Qs = dyn;
    float* Ksb = Qs + ABR * QKPAD;
    float* Vsb = Ksb + 2 * ABC * QKPAD;
    float* Ps = Vsb + 2 * ABC * QKPAD;

    int bh = blockIdx.x;                    // 0..23
    int h = bh % NHEAD;
    int b = bh / NHEAD;
    int qb = (TLEN / ABR - 1) - blockIdx.y; // heavy CTAs first
    int tid = threadIdx.x, lane = tid & 31, wid = tid >> 5;
    int gid = lane >> 2, tig = lane & 3;
    int wq = wid * 16;
    int q0 = qb * ABR;
    size_t baserow = (size_t)b * TLEN;
    int off = h * HDIM;
    const float scale = 0.08838834764831845f;

    for (int f = tid; f < ABR * 32; f += 256) {
        int r = f >> 5, c4 = (f & 31) * 4;
        float4 t = *reinterpret_cast<const float4*>(q + (baserow + q0 + r) * EDIM + off + c4);
        float* dst = &Qs[r * QKPAD + c4];
        dst[0] = t.x; dst[1] = t.y; dst[2] = t.z; dst[3] = t.w;
    }

    float o_acc[16][4];
#pragma unroll
    for (int n = 0; n < 16; n++)
#pragma unroll
        for (int i = 0; i < 4; i++) o_acc[n][i] = 0.f;
    float m0 = -1e30f, m1 = -1e30f, l0 = 0.f, l1 = 0.f;

    int ntile = 4 * qb + 4;

    {
        for (int f = tid; f < ABC * 32; f += 256) {
            int r = f >> 5, c4 = (f & 31) * 4;
            size_t g = (baserow + r) * EDIM + off + c4;
            cp16(&Ksb[r * QKPAD + c4], k + g);
            cp16(&Vsb[r * QKPAD + c4], v + g);
        }
        asm volatile("cp.async.commit_group;");
    }

    for (int kt = 0; kt < ntile; kt++) {
        int cur = kt & 1;
        if (kt + 1 < ntile) {
            int nxt = cur ^ 1;
            float* Kd = Ksb + nxt * ABC * QKPAD;
            float* Vd = Vsb + nxt * ABC * QKPAD;
            for (int f = tid; f < ABC * 32; f += 256) {
                int r = f >> 5, c4 = (f & 31) * 4;
                size_t g = (baserow + (kt + 1) * ABC + r) * EDIM + off + c4;
                cp16(&Kd[r * QKPAD + c4], k + g);
                cp16(&Vd[r * QKPAD + c4], v + g);
            }
            asm volatile("cp.async.commit_group;");
            asm volatile("cp.async.wait_group 1;");
        } else {
            asm volatile("cp.async.wait_group 0;");
        }
        __syncthreads();

        const float* Kb = Ksb + cur * ABC * QKPAD;
        const float* Vb = Vsb + cur * ABC * QKPAD;

        float sacc[4][4];
#pragma unroll
        for (int n = 0; n < 4; n++)
#pragma unroll
            for (int i = 0; i < 4; i++) sacc[n][i] = 0.f;

#pragma unroll
        for (int kk = 0; kk < HDIM; kk += 8) {
            const float* qr0 = &Qs[(wq + gid) * QKPAD + kk];
            const float* qr1 = &Qs[(wq + gid + 8) * QKPAD + kk];
            uint32_t a0 = __float_as_uint(qr0[tig]);
            uint32_t a1 = __float_as_uint(qr1[tig]);
            uint32_t a2 = __float_as_uint(qr0[tig + 4]);
            uint32_t a3 = __float_as_uint(qr1[tig + 4]);
#pragma unroll
            for (int n8 = 0; n8 < 4; n8++) {
                const float* kb = &Kb[(n8 * 8 + gid) * QKPAD + kk];
                uint32_t b0 = __float_as_uint(kb[tig]);
                uint32_t b1 = __float_as_uint(kb[tig + 4]);
                mma_tf32(sacc[n8], a0, a1, a2, a3, b0, b1);
            }
        }

        int qg0 = q0 + wq + gid;
        int qg1 = qg0 + 8;
        int kb0 = kt * ABC + tig * 2;
        float tm0 = -1e30f, tm1 = -1e30f;
#pragma unroll
        for (int n8 = 0; n8 < 4; n8++) {
            int c0 = kb0 + n8 * 8;
            float v0 = sacc[n8][0] * scale; if (c0 > qg0)     v0 = -1e30f;
            float v1 = sacc[n8][1] * scale; if (c0 + 1 > qg0) v1 = -1e30f;
            float v2 = sacc[n8][2] * scale; if (c0 > qg1)     v2 = -1e30f;
            float v3 = sacc[n8][3] * scale; if (c0 + 1 > qg1) v3 = -1e30f;
            sacc[n8][0] = v0; sacc[n8][1] = v1; sacc[n8][2] = v2; sacc[n8][3] = v3;
            tm0 = fmaxf(tm0, fmaxf(v0, v1));
            tm1 = fmaxf(tm1, fmaxf(v2, v3));
        }
        tm0 = fmaxf(tm0, __shfl_xor_sync(0xffffffffu, tm0, 1));
        tm0 = fmaxf(tm0, __shfl_xor_sync(0xffffffffu, tm0, 2));
        tm1 = fmaxf(tm1, __shfl_xor_sync(0xffffffffu, tm1, 1));
        tm1 = fmaxf(tm1, __shfl_xor_sync(0xffffffffu, tm1, 2));
        float mn0 = fmaxf(m0, tm0), mn1 = fmaxf(m1, tm1);
        float corr0 = __expf(m0 - mn0), corr1 = __expf(m1 - mn1);
        m0 = mn0; m1 = mn1;

        float ts0 = 0.f, ts1 = 0.f;
#pragma unroll
        for (int n8 = 0; n8 < 4; n8++) {
            float p0 = __expf(sacc[n8][0] - mn0);
            float p1 = __expf(sacc[n8][1] - mn0);
            float p2 = __expf(sacc[n8][2] - mn1);
            float p3 = __expf(sacc[n8][3] - mn1);
            ts0 += p0 + p1; ts1 += p2 + p3;
            float2 w0, w1;
            w0.x = __uint_as_float(f2tf32(p0)); w0.y = __uint_as_float(f2tf32(p1));
            w1.x = __uint_as_float(f2tf32(p2)); w1.y = __uint_as_float(f2tf32(p3));
            *reinterpret_cast<float2*>(&Ps[(wq + gid) * PPAD + n8 * 8 + tig * 2]) = w0;
            *reinterpret_cast<float2*>(&Ps[(wq + gid + 8) * PPAD + n8 * 8 + tig * 2]) = w1;
        }
        ts0 += __shfl_xor_sync(0xffffffffu, ts0, 1);
        ts0 += __shfl_xor_sync(0xffffffffu, ts0, 2);
        ts1 += __shfl_xor_sync(0xffffffffu, ts1, 1);
        ts1 += __shfl_xor_sync(0xffffffffu, ts1, 2);
        l0 = l0 * corr0 + ts0;
        l1 = l1 * corr1 + ts1;

#pragma unroll
        for (int n = 0; n < 16; n++) {
            o_acc[n][0] *= corr0; o_acc[n][1] *= corr0;
            o_acc[n][2] *= corr1; o_acc[n][3] *= corr1;
        }
        __syncwarp();

#pragma unroll
        for (int kk = 0; kk < ABC; kk += 8) {
            const float* pr0 = &Ps[(wq + gid) * PPAD + kk];
            const float* pr1 = &Ps[(wq + gid + 8) * PPAD + kk];
            uint32_t a0 = __float_as_uint(pr0[tig]);
            uint32_t a1 = __float_as_uint(pr1[tig]);
            uint32_t a2 = __float_as_uint(pr0[tig + 4]);
            uint32_t a3 = __float_as_uint(pr1[tig + 4]);
#pragma unroll
            for (int n8 = 0; n8 < 16; n8++) {
                uint32_t b0 = __float_as_uint(Vb[(kk + tig) * QKPAD + n8 * 8 + gid]);
                uint32_t b1 = __float_as_uint(Vb[(kk + tig + 4) * QKPAD + n8 * 8 + gid]);
                mma_tf32(o_acc[n8], a0, a1, a2, a3, b0, b1);
            }
        }
        __syncwarp();
        __syncthreads();
    }

    float inv0 = 1.f / l0, inv1 = 1.f / l1;
    size_t ar0 = (baserow + q0 + wq + gid) * EDIM + off;
    size_t ar1 = (baserow + q0 + wq + gid + 8) * EDIM + off;
#pragma unroll
    for (int n8 = 0; n8 < 16; n8++) {
        int col = n8 * 8 + tig * 2;
        float2 o0; o0.x = o_acc[n8][0] * inv0; o0.y = o_acc[n8][1] * inv0;
        float2 o1; o1.x = o_acc[n8][2] * inv1; o1.y = o_acc[n8][3] * inv1;
        *reinterpret_cast<float2*>(out + ar0 + col) = o0;
        *reinterpret_cast<float2*>(out + ar1 + col) = o1;
    }
}

// ---------------- loss: single-pass online log-softmax NLL (R8-exact) -------
__global__ void __launch_bounds__(256) loss_row_kernel(const float* __restrict__ logits,
                                                       const int* __restrict__ tgt,
                                                       float* __restrict__ rowloss) {
    __shared__ float shm[8], shs[8];
    int r = blockIdx.x;
    int tid = threadIdx.x, lane = tid & 31, wid = tid >> 5;
    const float* p = logits + (size_t)r * VOCAB;
    float m = -1e30f, s = 0.f;
    for (int j = tid; j < VOCAB; j += 256) {
        float vv = p[j];
        float mn = fmaxf(m, vv);
        s = s * __expf(m - mn) + __expf(vv - mn);
        m = mn;
    }
#pragma unroll
    for (int o = 16; o; o >>= 1) {
        float om = __shfl_xor_sync(0xffffffffu, m, o);
        float os = __shfl_xor_sync(0xffffffffu, s, o);
        float mn = fmaxf(m, om);
        s = s * __expf(m - mn) + os * __expf(om - mn);
        m = mn;
    }
    if (lane == 0) { shm[wid] = m; shs[wid] = s; }
    __syncthreads();
    if (tid == 0) {
        float mm = shm[0], ss = shs[0];
        for (int i = 1; i < 8; i++) {
            float mn = fmaxf(mm, shm[i]);
            ss = ss * __expf(mm - mn) + shs[i] * __expf(shm[i] - mn);
            mm = mn;
        }
        int tg = tgt[r];
        rowloss[r] = -(p[tg] - mm - logf(ss));
    }
}

__global__ void __launch_bounds__(256) loss_fin_kernel(const float* __restrict__ rl,
                                                       float* __restrict__ out) {
    __shared__ float sh[8];
    int tid = threadIdx.x, lane = tid & 31, wid = tid >> 5;
    float s = 0.f;
    for (int i = tid; i < NROWS; i += 256) s += rl[i];
#pragma unroll
    for (int o = 16; o; o >>= 1) s += __shfl_xor_sync(0xffffffffu, s, o);
    if (lane == 0) sh[wid] = s;
    __syncthreads();
    if (tid == 0) {
        float t = 0.f; for (int i = 0; i < 8; i++) t += sh[i];
        out[0] = t * (1.0f / NROWS);
    }
}

// ---------------- host orchestration ---------------------------------------
extern "C" void kernel_launch(void* const* d_in, const int* in_sizes, int n_in,
                              void* d_out, int out_size) {
    const int* idx   = (const int*)d_in[0];
    const int* tgt   = (const int*)d_in[1];
    const float* tok  = (const float*)d_in[2];
    const float* pos  = (const float*)d_in[3];
    const float* Wq   = (const float*)d_in[4];
    const float* bq   = (const float*)d_in[5];
    const float* Wk   = (const float*)d_in[6];
    const float* bk   = (const float*)d_in[7];
    const float* Wv   = (const float*)d_in[8];
    const float* bv   = (const float*)d_in[9];
    const float* Wo   = (const float*)d_in[10];
    const float* bo   = (const float*)d_in[11];
    const float* w1   = (const float*)d_in[12];
    const float* b1   = (const float*)d_in[13];
    const float* w2   = (const float*)d_in[14];
    const float* b2   = (const float*)d_in[15];
    const float* ln1s = (const float*)d_in[16];
    const float* ln1b = (const float*)d_in[17];
    const float* ln2s = (const float*)d_in[18];
    const float* ln2b = (const float*)d_in[19];
    const float* lnfs = (const float*)d_in[20];
    const float* lnfb = (const float*)d_in[21];
    const float* Wlm  = (const float*)d_in[22];
    const float* blm  = (const float*)d_in[23];
    float* out = (float*)d_out;

    float *x, *h, *q, *k, *v, *att, *mid, *rl;
    cudaGetSymbolAddress((void**)&x,   g_x);
    cudaGetSymbolAddress((void**)&h,   g_h);
    cudaGetSymbolAddress((void**)&q,   g_q);
    cudaGetSymbolAddress((void**)&k,   g_k);
    cudaGetSymbolAddress((void**)&v,   g_v);
    cudaGetSymbolAddress((void**)&att, g_att);
    cudaGetSymbolAddress((void**)&mid, g_mid);
    cudaGetSymbolAddress((void**)&rl,  g_rowloss);

    cudaFuncSetAttribute(attn_tc_kernel, cudaFuncAttributeMaxDynamicSharedMemorySize, ATTN_SMEM);
    cudaFuncSetAttribute(tgemm_kernel, cudaFuncAttributeMaxDynamicSharedMemorySize, GEMM_SMEM);
    cudaFuncSetAttribute(qkv_kernel, cudaFuncAttributeMaxDynamicSharedMemorySize, GEMM_SMEM);

    embed_kernel<<<NROWS, 256>>>(idx, tok, pos, x);

    dim3 gProj(EDIM / 128, NROWS / 128);
    dim3 gQkv(EDIM / 128, NROWS / 128, 3);
    dim3 gMlp1(FFDIM / 128, NROWS / 128);
    dim3 gLm(VOCAB / 128, NROWS / 128);
    dim3 gAttn(NHEAD * BATCH, TLEN / ABR);   // 24 x 8; qb slowest, reversed

    for (int l = 0; l < NLAYER; l++) {
        size_t wo = (size_t)l * EDIM * EDIM;
        size_t w1o = (size_t)l * EDIM * FFDIM;
        ln_kernel<<<NROWS, 256>>>(x, ln1s + l * EDIM, ln1b + l * EDIM, h);
        qkv_kernel<<<gQkv, 256, GEMM_SMEM>>>(h, Wq + wo, Wk + wo, Wv + wo,
                                  bq + l * EDIM, bk + l * EDIM, bv + l * EDIM, q, k, v);
        attn_tc_kernel<<<gAttn, 256, ATTN_SMEM>>>(q, k, v, att);
        tgemm_kernel<<<gProj, 256, GEMM_SMEM>>>(att, Wo + wo, bo + l * EDIM, x, x, EDIM, EDIM, 1 | 4);
        ln_kernel<<<NROWS, 256>>>(x, ln2s + l * EDIM, ln2b + l * EDIM, h);
        tgemm_kernel<<<gMlp1, 256, GEMM_SMEM>>>(h, w1 + w1o, b1 + (size_t)l * FFDIM, nullptr, mid, FFDIM, EDIM, 1 | 2);
        tgemm_kernel<<<gProj, 256, GEMM_SMEM>>>(mid, w2 + w1o, b2 + l * EDIM, x, x, EDIM, FFDIM, 1 | 4);
    }
    ln_kernel<<<NROWS, 256>>>(x, lnfs, lnfb, h);
    tgemm_kernel<<<gLm, 256, GEMM_SMEM>>>(h, Wlm, blm, nullptr, out, VOCAB, EDIM, 1);

    if (out_size > NROWS * VOCAB) {
        loss_row_kernel<<<NROWS, 256>>>(out, tgt, rl);
        loss_fin_kernel<<<1, 256>>>(rl, out + (size_t)NROWS * VOCAB);
    }
}